// round 6
// baseline (speedup 1.0000x reference)
#include <cuda_runtime.h>

// PointConv B=4, N=16384, K=32, D=64.
// out[p,g] = sum_k ( leaky_relu((pos[p]-pos[j_k]) @ W1 + b1) @ W2 + b2 )[g] * x[j_k,g]
//
// One warp per point. Lane owns output channels g0=2*lane, g1=2*lane+1.
// f32x2 packing over f-PAIRS (even f in lo, odd f in hi):
//   multiplier  : (h[2i], h[2i+1])   — natural pairs from contiguous smem h, LDS.128
//   multiplicand: (W2[2i][g], W2[2i+1][g]) — register resident per g (128 regs total)
// 16 LDS.128 + 64 f2_fma per neighbor. rel-pos+idx broadcast via one smem float4
// per k (no shfl). Two neighbors per iteration, single __syncwarp per iteration.

#define NPTS   16384
#define BATCH  4
#define DM     64
#define KN     32
#define BN_TOTAL (BATCH * NPTS)

typedef unsigned long long u64;

__device__ __forceinline__ u64 f2_fma(u64 a, u64 b, u64 c) {
    u64 d;
    asm("fma.rn.f32x2 %0, %1, %2, %3;" : "=l"(d) : "l"(a), "l"(b), "l"(c));
    return d;
}
__device__ __forceinline__ u64 f2_add(u64 a, u64 b) {
    u64 d;
    asm("add.rn.f32x2 %0, %1, %2;" : "=l"(d) : "l"(a), "l"(b));
    return d;
}
__device__ __forceinline__ u64 f2_pack(float lo, float hi) {
    u64 d;
    asm("mov.b64 %0, {%1, %2};" : "=l"(d) : "f"(lo), "f"(hi));
    return d;
}
__device__ __forceinline__ float f2_hsum(u64 a) {
    float lo, hi;
    asm("mov.b64 {%0, %1}, %2;" : "=f"(lo), "=f"(hi) : "l"(a));
    return lo + hi;
}

__global__ void __launch_bounds__(128, 3) pointconv_kernel(
    const float* __restrict__ x,    // [B*N, 64]
    const float* __restrict__ pos,  // [B*N, 3]
    const int*   __restrict__ nidx, // [B*N, 32]
    const float* __restrict__ W1,   // [3, 64]
    const float* __restrict__ b1,   // [64]
    const float* __restrict__ W2,   // [64, 64]
    const float* __restrict__ b2,   // [64]
    float*       __restrict__ out)  // [B*N, 64]
{
    const int lane  = threadIdx.x & 31;
    const int warp  = threadIdx.x >> 5;
    const int point = blockIdx.x * 4 + warp;
    const long base = (long)(point >> 14) * NPTS;   // batch row offset

    // per-warp staging
    __shared__ __align__(16) float4 relbuf[4][KN];     // (rx, ry, rz, idx-as-float)
    __shared__ __align__(16) float  hs[4][4][DM];      // 4 rotating h buffers

    // ---- W2 f-pair registers for g0=2*lane, g1=2*lane+1 ----
    // w2g0[i] = (W2[2i][g0], W2[2i+1][g0]),  w2g1[i] = (..g1..)
    u64 w2g0[32], w2g1[32];
    {
        const float2* W2v = reinterpret_cast<const float2*>(W2);
        #pragma unroll
        for (int i = 0; i < 32; ++i) {
            const float2 r0 = W2v[(2 * i)     * 32 + lane];
            const float2 r1 = W2v[(2 * i + 1) * 32 + lane];
            w2g0[i] = f2_pack(r0.x, r1.x);
            w2g1[i] = f2_pack(r0.y, r1.y);
        }
    }

    // ---- W1/b1 for hidden channels f0=lane, f1=lane+32 ----
    const float w1xa = W1[0 * DM + lane],  w1xb = W1[0 * DM + lane + 32];
    const float w1ya = W1[1 * DM + lane],  w1yb = W1[1 * DM + lane + 32];
    const float w1za = W1[2 * DM + lane],  w1zb = W1[2 * DM + lane + 32];
    const float b1a  = b1[lane],           b1b  = b1[lane + 32];
    const float2 b2v = reinterpret_cast<const float2*>(b2)[lane];

    // ---- center pos, own neighbor (k = lane), stage rel-pos + idx ----
    {
        const float px = pos[(long)point * 3 + 0];
        const float py = pos[(long)point * 3 + 1];
        const float pz = pos[(long)point * 3 + 2];
        const int myidx = nidx[(long)point * KN + lane];
        const float* pj = pos + (base + myidx) * 3;
        relbuf[warp][lane] = make_float4(px - __ldg(pj + 0),
                                         py - __ldg(pj + 1),
                                         pz - __ldg(pj + 2),
                                         __int_as_float(myidx));
    }
    __syncwarp();

    float acc0x = 0.f, acc0y = 0.f, acc1x = 0.f, acc1y = 0.f;

    #pragma unroll 1
    for (int k2 = 0; k2 < KN / 2; ++k2) {
        const int s = (k2 & 1) * 2;   // rotating buffer pair {s, s+1}

        // broadcast rel-pos + idx for both neighbors (LDS.128 each)
        const float4 rp0 = relbuf[warp][2 * k2];
        const float4 rp1 = relbuf[warp][2 * k2 + 1];
        const int j0 = __float_as_int(rp0.w);
        const int j1 = __float_as_int(rp1.w);

        // hidden activations: this lane's two f-channels, both neighbors
        float za0 = fmaf(rp0.x, w1xa, fmaf(rp0.y, w1ya, fmaf(rp0.z, w1za, b1a)));
        float zb0 = fmaf(rp0.x, w1xb, fmaf(rp0.y, w1yb, fmaf(rp0.z, w1zb, b1b)));
        float za1 = fmaf(rp1.x, w1xa, fmaf(rp1.y, w1ya, fmaf(rp1.z, w1za, b1a)));
        float zb1 = fmaf(rp1.x, w1xb, fmaf(rp1.y, w1yb, fmaf(rp1.z, w1zb, b1b)));
        hs[warp][s][lane]          = fmaxf(za0, 0.f) + 0.1f * fminf(za0, 0.f);
        hs[warp][s][lane + 32]     = fmaxf(zb0, 0.f) + 0.1f * fminf(zb0, 0.f);
        hs[warp][s + 1][lane]      = fmaxf(za1, 0.f) + 0.1f * fminf(za1, 0.f);
        hs[warp][s + 1][lane + 32] = fmaxf(zb1, 0.f) + 0.1f * fminf(zb1, 0.f);

        // x gathers for both neighbors (L2-resident, coalesced) — issue early
        const float2 xv0 = reinterpret_cast<const float2*>(x + (base + j0) * DM)[lane];
        const float2 xv1 = reinterpret_cast<const float2*>(x + (base + j1) * DM)[lane];

        __syncwarp();

        // ---- matvec neighbor k0: 16 LDS.128, 64 f2_fma, 4 chains ----
        {
            const ulonglong2* hq = reinterpret_cast<const ulonglong2*>(hs[warp][s]);
            u64 c0 = 0ull, c1 = 0ull, c2 = 0ull, c3 = 0ull;
            #pragma unroll
            for (int i = 0; i < 16; ++i) {
                const ulonglong2 v = hq[i];      // (h4i,h4i+1),(h4i+2,h4i+3)
                c0 = f2_fma(v.x, w2g0[2 * i],     c0);
                c1 = f2_fma(v.y, w2g0[2 * i + 1], c1);
                c2 = f2_fma(v.x, w2g1[2 * i],     c2);
                c3 = f2_fma(v.y, w2g1[2 * i + 1], c3);
            }
            const float wg0 = f2_hsum(f2_add(c0, c1)) + b2v.x;
            const float wg1 = f2_hsum(f2_add(c2, c3)) + b2v.y;
            acc0x = fmaf(wg0, xv0.x, acc0x);
            acc0y = fmaf(wg1, xv0.y, acc0y);
        }

        // ---- matvec neighbor k1 ----
        {
            const ulonglong2* hq = reinterpret_cast<const ulonglong2*>(hs[warp][s + 1]);
            u64 c0 = 0ull, c1 = 0ull, c2 = 0ull, c3 = 0ull;
            #pragma unroll
            for (int i = 0; i < 16; ++i) {
                const ulonglong2 v = hq[i];
                c0 = f2_fma(v.x, w2g0[2 * i],     c0);
                c1 = f2_fma(v.y, w2g0[2 * i + 1], c1);
                c2 = f2_fma(v.x, w2g1[2 * i],     c2);
                c3 = f2_fma(v.y, w2g1[2 * i + 1], c3);
            }
            const float wg0 = f2_hsum(f2_add(c0, c1)) + b2v.x;
            const float wg1 = f2_hsum(f2_add(c2, c3)) + b2v.y;
            acc1x = fmaf(wg0, xv1.x, acc1x);
            acc1y = fmaf(wg1, xv1.y, acc1y);
        }
    }

    reinterpret_cast<float2*>(out)[(long)point * 32 + lane] =
        make_float2(acc0x + acc1x, acc0y + acc1y);
}

extern "C" void kernel_launch(void* const* d_in, const int* in_sizes, int n_in,
                              void* d_out, int out_size) {
    const float* x   = (const float*)d_in[0];
    const float* pos = (const float*)d_in[1];
    const int*   idx = (const int*)d_in[2];
    const float* W1  = (const float*)d_in[3];
    const float* b1  = (const float*)d_in[4];
    const float* W2  = (const float*)d_in[5];
    const float* b2  = (const float*)d_in[6];
    float*       out = (float*)d_out;

    pointconv_kernel<<<BN_TOTAL / 4, 128>>>(x, pos, idx, W1, b1, W2, b2, out);
}

// round 7
// speedup vs baseline: 1.0522x; 1.0522x over previous
#include <cuda_runtime.h>

// PointConv B=4, N=16384, K=32, D=64.
// out[p,g] = sum_k ( leaky_relu((pos[p]-pos[j_k]) @ W1 + b1) @ W2 + b2 )[g] * x[j_k,g]
//
// One warp per point. Lane owns output channels g0=2*lane, g1=2*lane+1.
// f32x2 packing over f-PAIRS (even f in lo, odd f in hi):
//   multiplier  : (h[2i], h[2i+1])   — natural pairs from contiguous smem h, LDS.128
//   multiplicand: (W2[2i][g], W2[2i+1][g]) — register resident per g (128 regs total)
// 16 LDS.128 + 64 f2_fma per neighbor. rel-pos+idx broadcast via one smem float4
// per k (no shfl). Two neighbors per iteration, single __syncwarp per iteration.

#define NPTS   16384
#define BATCH  4
#define DM     64
#define KN     32
#define BN_TOTAL (BATCH * NPTS)

typedef unsigned long long u64;

__device__ __forceinline__ u64 f2_fma(u64 a, u64 b, u64 c) {
    u64 d;
    asm("fma.rn.f32x2 %0, %1, %2, %3;" : "=l"(d) : "l"(a), "l"(b), "l"(c));
    return d;
}
__device__ __forceinline__ u64 f2_add(u64 a, u64 b) {
    u64 d;
    asm("add.rn.f32x2 %0, %1, %2;" : "=l"(d) : "l"(a), "l"(b));
    return d;
}
__device__ __forceinline__ u64 f2_pack(float lo, float hi) {
    u64 d;
    asm("mov.b64 %0, {%1, %2};" : "=l"(d) : "f"(lo), "f"(hi));
    return d;
}
__device__ __forceinline__ float f2_hsum(u64 a) {
    float lo, hi;
    asm("mov.b64 {%0, %1}, %2;" : "=f"(lo), "=f"(hi) : "l"(a));
    return lo + hi;
}

__global__ void __launch_bounds__(128, 3) pointconv_kernel(
    const float* __restrict__ x,    // [B*N, 64]
    const float* __restrict__ pos,  // [B*N, 3]
    const int*   __restrict__ nidx, // [B*N, 32]
    const float* __restrict__ W1,   // [3, 64]
    const float* __restrict__ b1,   // [64]
    const float* __restrict__ W2,   // [64, 64]
    const float* __restrict__ b2,   // [64]
    float*       __restrict__ out)  // [B*N, 64]
{
    const int lane  = threadIdx.x & 31;
    const int warp  = threadIdx.x >> 5;
    const int point = blockIdx.x * 4 + warp;
    const long base = (long)(point >> 14) * NPTS;   // batch row offset

    // per-warp staging
    __shared__ __align__(16) float4 relbuf[4][KN];     // (rx, ry, rz, idx-as-float)
    __shared__ __align__(16) float  hs[4][4][DM];      // 4 rotating h buffers

    // ---- W2 f-pair registers for g0=2*lane, g1=2*lane+1 ----
    // w2g0[i] = (W2[2i][g0], W2[2i+1][g0]),  w2g1[i] = (..g1..)
    u64 w2g0[32], w2g1[32];
    {
        const float2* W2v = reinterpret_cast<const float2*>(W2);
        #pragma unroll
        for (int i = 0; i < 32; ++i) {
            const float2 r0 = W2v[(2 * i)     * 32 + lane];
            const float2 r1 = W2v[(2 * i + 1) * 32 + lane];
            w2g0[i] = f2_pack(r0.x, r1.x);
            w2g1[i] = f2_pack(r0.y, r1.y);
        }
    }

    // ---- W1/b1 for hidden channels f0=lane, f1=lane+32 ----
    const float w1xa = W1[0 * DM + lane],  w1xb = W1[0 * DM + lane + 32];
    const float w1ya = W1[1 * DM + lane],  w1yb = W1[1 * DM + lane + 32];
    const float w1za = W1[2 * DM + lane],  w1zb = W1[2 * DM + lane + 32];
    const float b1a  = b1[lane],           b1b  = b1[lane + 32];
    const float2 b2v = reinterpret_cast<const float2*>(b2)[lane];

    // ---- center pos, own neighbor (k = lane), stage rel-pos + idx ----
    {
        const float px = pos[(long)point * 3 + 0];
        const float py = pos[(long)point * 3 + 1];
        const float pz = pos[(long)point * 3 + 2];
        const int myidx = nidx[(long)point * KN + lane];
        const float* pj = pos + (base + myidx) * 3;
        relbuf[warp][lane] = make_float4(px - __ldg(pj + 0),
                                         py - __ldg(pj + 1),
                                         pz - __ldg(pj + 2),
                                         __int_as_float(myidx));
    }
    __syncwarp();

    float acc0x = 0.f, acc0y = 0.f, acc1x = 0.f, acc1y = 0.f;

    #pragma unroll 1
    for (int k2 = 0; k2 < KN / 2; ++k2) {
        const int s = (k2 & 1) * 2;   // rotating buffer pair {s, s+1}

        // broadcast rel-pos + idx for both neighbors (LDS.128 each)
        const float4 rp0 = relbuf[warp][2 * k2];
        const float4 rp1 = relbuf[warp][2 * k2 + 1];
        const int j0 = __float_as_int(rp0.w);
        const int j1 = __float_as_int(rp1.w);

        // hidden activations: this lane's two f-channels, both neighbors
        float za0 = fmaf(rp0.x, w1xa, fmaf(rp0.y, w1ya, fmaf(rp0.z, w1za, b1a)));
        float zb0 = fmaf(rp0.x, w1xb, fmaf(rp0.y, w1yb, fmaf(rp0.z, w1zb, b1b)));
        float za1 = fmaf(rp1.x, w1xa, fmaf(rp1.y, w1ya, fmaf(rp1.z, w1za, b1a)));
        float zb1 = fmaf(rp1.x, w1xb, fmaf(rp1.y, w1yb, fmaf(rp1.z, w1zb, b1b)));
        hs[warp][s][lane]          = fmaxf(za0, 0.f) + 0.1f * fminf(za0, 0.f);
        hs[warp][s][lane + 32]     = fmaxf(zb0, 0.f) + 0.1f * fminf(zb0, 0.f);
        hs[warp][s + 1][lane]      = fmaxf(za1, 0.f) + 0.1f * fminf(za1, 0.f);
        hs[warp][s + 1][lane + 32] = fmaxf(zb1, 0.f) + 0.1f * fminf(zb1, 0.f);

        // x gathers for both neighbors (L2-resident, coalesced) — issue early
        const float2 xv0 = reinterpret_cast<const float2*>(x + (base + j0) * DM)[lane];
        const float2 xv1 = reinterpret_cast<const float2*>(x + (base + j1) * DM)[lane];

        __syncwarp();

        // ---- matvec neighbor k0: 16 LDS.128, 64 f2_fma, 4 chains ----
        {
            const ulonglong2* hq = reinterpret_cast<const ulonglong2*>(hs[warp][s]);
            u64 c0 = 0ull, c1 = 0ull, c2 = 0ull, c3 = 0ull;
            #pragma unroll
            for (int i = 0; i < 16; ++i) {
                const ulonglong2 v = hq[i];      // (h4i,h4i+1),(h4i+2,h4i+3)
                c0 = f2_fma(v.x, w2g0[2 * i],     c0);
                c1 = f2_fma(v.y, w2g0[2 * i + 1], c1);
                c2 = f2_fma(v.x, w2g1[2 * i],     c2);
                c3 = f2_fma(v.y, w2g1[2 * i + 1], c3);
            }
            const float wg0 = f2_hsum(f2_add(c0, c1)) + b2v.x;
            const float wg1 = f2_hsum(f2_add(c2, c3)) + b2v.y;
            acc0x = fmaf(wg0, xv0.x, acc0x);
            acc0y = fmaf(wg1, xv0.y, acc0y);
        }

        // ---- matvec neighbor k1 ----
        {
            const ulonglong2* hq = reinterpret_cast<const ulonglong2*>(hs[warp][s + 1]);
            u64 c0 = 0ull, c1 = 0ull, c2 = 0ull, c3 = 0ull;
            #pragma unroll
            for (int i = 0; i < 16; ++i) {
                const ulonglong2 v = hq[i];
                c0 = f2_fma(v.x, w2g0[2 * i],     c0);
                c1 = f2_fma(v.y, w2g0[2 * i + 1], c1);
                c2 = f2_fma(v.x, w2g1[2 * i],     c2);
                c3 = f2_fma(v.y, w2g1[2 * i + 1], c3);
            }
            const float wg0 = f2_hsum(f2_add(c0, c1)) + b2v.x;
            const float wg1 = f2_hsum(f2_add(c2, c3)) + b2v.y;
            acc1x = fmaf(wg0, xv1.x, acc1x);
            acc1y = fmaf(wg1, xv1.y, acc1y);
        }
    }

    reinterpret_cast<float2*>(out)[(long)point * 32 + lane] =
        make_float2(acc0x + acc1x, acc0y + acc1y);
}

extern "C" void kernel_launch(void* const* d_in, const int* in_sizes, int n_in,
                              void* d_out, int out_size) {
    const float* x   = (const float*)d_in[0];
    const float* pos = (const float*)d_in[1];
    const int*   idx = (const int*)d_in[2];
    const float* W1  = (const float*)d_in[3];
    const float* b1  = (const float*)d_in[4];
    const float* W2  = (const float*)d_in[5];
    const float* b2  = (const float*)d_in[6];
    float*       out = (float*)d_out;

    pointconv_kernel<<<BN_TOTAL / 4, 128>>>(x, pos, idx, W1, b1, W2, b2, out);
}

// round 8
// speedup vs baseline: 1.0535x; 1.0012x over previous
#include <cuda_runtime.h>

// PointConv B=4, N=16384, K=32, D=64.
// out[p,g] = sum_k ( leaky_relu((pos[p]-pos[j_k]) @ W1 + b1) @ W2 + b2 )[g] * x[j_k,g]
//
// One warp per point. Lane owns output channels g0=2*lane, g1=2*lane+1.
// f32x2 packing over f-PAIRS (even f in lo, odd f in hi):
//   multiplier  : (h[2i], h[2i+1])   — natural pairs from contiguous smem h, LDS.128
//   multiplicand: (W2[2i][g], W2[2i+1][g]) — register resident per g (128 regs total)
// 16 LDS.128 + 64 f2_fma per neighbor. rel-pos+idx broadcast via one smem float4
// per k (no shfl). Two neighbors per iteration, single __syncwarp per iteration.

#define NPTS   16384
#define BATCH  4
#define DM     64
#define KN     32
#define BN_TOTAL (BATCH * NPTS)

typedef unsigned long long u64;

__device__ __forceinline__ u64 f2_fma(u64 a, u64 b, u64 c) {
    u64 d;
    asm("fma.rn.f32x2 %0, %1, %2, %3;" : "=l"(d) : "l"(a), "l"(b), "l"(c));
    return d;
}
__device__ __forceinline__ u64 f2_add(u64 a, u64 b) {
    u64 d;
    asm("add.rn.f32x2 %0, %1, %2;" : "=l"(d) : "l"(a), "l"(b));
    return d;
}
__device__ __forceinline__ u64 f2_pack(float lo, float hi) {
    u64 d;
    asm("mov.b64 %0, {%1, %2};" : "=l"(d) : "f"(lo), "f"(hi));
    return d;
}
__device__ __forceinline__ float f2_hsum(u64 a) {
    float lo, hi;
    asm("mov.b64 {%0, %1}, %2;" : "=f"(lo), "=f"(hi) : "l"(a));
    return lo + hi;
}

__global__ void __launch_bounds__(128, 3) pointconv_kernel(
    const float* __restrict__ x,    // [B*N, 64]
    const float* __restrict__ pos,  // [B*N, 3]
    const int*   __restrict__ nidx, // [B*N, 32]
    const float* __restrict__ W1,   // [3, 64]
    const float* __restrict__ b1,   // [64]
    const float* __restrict__ W2,   // [64, 64]
    const float* __restrict__ b2,   // [64]
    float*       __restrict__ out)  // [B*N, 64]
{
    const int lane  = threadIdx.x & 31;
    const int warp  = threadIdx.x >> 5;
    const int point = blockIdx.x * 4 + warp;
    const long base = (long)(point >> 14) * NPTS;   // batch row offset

    // per-warp staging
    __shared__ __align__(16) float4 relbuf[4][KN];     // (rx, ry, rz, idx-as-float)
    __shared__ __align__(16) float  hs[4][4][DM];      // 4 rotating h buffers

    // ---- W2 f-pair registers for g0=2*lane, g1=2*lane+1 ----
    // w2g0[i] = (W2[2i][g0], W2[2i+1][g0]),  w2g1[i] = (..g1..)
    u64 w2g0[32], w2g1[32];
    {
        const float2* W2v = reinterpret_cast<const float2*>(W2);
        #pragma unroll
        for (int i = 0; i < 32; ++i) {
            const float2 r0 = W2v[(2 * i)     * 32 + lane];
            const float2 r1 = W2v[(2 * i + 1) * 32 + lane];
            w2g0[i] = f2_pack(r0.x, r1.x);
            w2g1[i] = f2_pack(r0.y, r1.y);
        }
    }

    // ---- W1/b1 for hidden channels f0=lane, f1=lane+32 ----
    const float w1xa = W1[0 * DM + lane],  w1xb = W1[0 * DM + lane + 32];
    const float w1ya = W1[1 * DM + lane],  w1yb = W1[1 * DM + lane + 32];
    const float w1za = W1[2 * DM + lane],  w1zb = W1[2 * DM + lane + 32];
    const float b1a  = b1[lane],           b1b  = b1[lane + 32];
    const float2 b2v = reinterpret_cast<const float2*>(b2)[lane];

    // ---- center pos, own neighbor (k = lane), stage rel-pos + idx ----
    {
        const float px = pos[(long)point * 3 + 0];
        const float py = pos[(long)point * 3 + 1];
        const float pz = pos[(long)point * 3 + 2];
        const int myidx = nidx[(long)point * KN + lane];
        const float* pj = pos + (base + myidx) * 3;
        relbuf[warp][lane] = make_float4(px - __ldg(pj + 0),
                                         py - __ldg(pj + 1),
                                         pz - __ldg(pj + 2),
                                         __int_as_float(myidx));
    }
    __syncwarp();

    float acc0x = 0.f, acc0y = 0.f, acc1x = 0.f, acc1y = 0.f;

    #pragma unroll 1
    for (int k2 = 0; k2 < KN / 2; ++k2) {
        const int s = (k2 & 1) * 2;   // rotating buffer pair {s, s+1}

        // broadcast rel-pos + idx for both neighbors (LDS.128 each)
        const float4 rp0 = relbuf[warp][2 * k2];
        const float4 rp1 = relbuf[warp][2 * k2 + 1];
        const int j0 = __float_as_int(rp0.w);
        const int j1 = __float_as_int(rp1.w);

        // hidden activations: this lane's two f-channels, both neighbors
        float za0 = fmaf(rp0.x, w1xa, fmaf(rp0.y, w1ya, fmaf(rp0.z, w1za, b1a)));
        float zb0 = fmaf(rp0.x, w1xb, fmaf(rp0.y, w1yb, fmaf(rp0.z, w1zb, b1b)));
        float za1 = fmaf(rp1.x, w1xa, fmaf(rp1.y, w1ya, fmaf(rp1.z, w1za, b1a)));
        float zb1 = fmaf(rp1.x, w1xb, fmaf(rp1.y, w1yb, fmaf(rp1.z, w1zb, b1b)));
        hs[warp][s][lane]          = fmaxf(za0, 0.f) + 0.1f * fminf(za0, 0.f);
        hs[warp][s][lane + 32]     = fmaxf(zb0, 0.f) + 0.1f * fminf(zb0, 0.f);
        hs[warp][s + 1][lane]      = fmaxf(za1, 0.f) + 0.1f * fminf(za1, 0.f);
        hs[warp][s + 1][lane + 32] = fmaxf(zb1, 0.f) + 0.1f * fminf(zb1, 0.f);

        // x gathers for both neighbors (L2-resident, coalesced) — issue early
        const float2 xv0 = reinterpret_cast<const float2*>(x + (base + j0) * DM)[lane];
        const float2 xv1 = reinterpret_cast<const float2*>(x + (base + j1) * DM)[lane];

        __syncwarp();

        // ---- matvec neighbor k0: 16 LDS.128, 64 f2_fma, 4 chains ----
        {
            const ulonglong2* hq = reinterpret_cast<const ulonglong2*>(hs[warp][s]);
            u64 c0 = 0ull, c1 = 0ull, c2 = 0ull, c3 = 0ull;
            #pragma unroll
            for (int i = 0; i < 16; ++i) {
                const ulonglong2 v = hq[i];      // (h4i,h4i+1),(h4i+2,h4i+3)
                c0 = f2_fma(v.x, w2g0[2 * i],     c0);
                c1 = f2_fma(v.y, w2g0[2 * i + 1], c1);
                c2 = f2_fma(v.x, w2g1[2 * i],     c2);
                c3 = f2_fma(v.y, w2g1[2 * i + 1], c3);
            }
            const float wg0 = f2_hsum(f2_add(c0, c1)) + b2v.x;
            const float wg1 = f2_hsum(f2_add(c2, c3)) + b2v.y;
            acc0x = fmaf(wg0, xv0.x, acc0x);
            acc0y = fmaf(wg1, xv0.y, acc0y);
        }

        // ---- matvec neighbor k1 ----
        {
            const ulonglong2* hq = reinterpret_cast<const ulonglong2*>(hs[warp][s + 1]);
            u64 c0 = 0ull, c1 = 0ull, c2 = 0ull, c3 = 0ull;
            #pragma unroll
            for (int i = 0; i < 16; ++i) {
                const ulonglong2 v = hq[i];
                c0 = f2_fma(v.x, w2g0[2 * i],     c0);
                c1 = f2_fma(v.y, w2g0[2 * i + 1], c1);
                c2 = f2_fma(v.x, w2g1[2 * i],     c2);
                c3 = f2_fma(v.y, w2g1[2 * i + 1], c3);
            }
            const float wg0 = f2_hsum(f2_add(c0, c1)) + b2v.x;
            const float wg1 = f2_hsum(f2_add(c2, c3)) + b2v.y;
            acc1x = fmaf(wg0, xv1.x, acc1x);
            acc1y = fmaf(wg1, xv1.y, acc1y);
        }
    }

    reinterpret_cast<float2*>(out)[(long)point * 32 + lane] =
        make_float2(acc0x + acc1x, acc0y + acc1y);
}

extern "C" void kernel_launch(void* const* d_in, const int* in_sizes, int n_in,
                              void* d_out, int out_size) {
    const float* x   = (const float*)d_in[0];
    const float* pos = (const float*)d_in[1];
    const int*   idx = (const int*)d_in[2];
    const float* W1  = (const float*)d_in[3];
    const float* b1  = (const float*)d_in[4];
    const float* W2  = (const float*)d_in[5];
    const float* b2  = (const float*)d_in[6];
    float*       out = (float*)d_out;

    pointconv_kernel<<<BN_TOTAL / 4, 128>>>(x, pos, idx, W1, b1, W2, b2, out);
}